// round 14
// baseline (speedup 1.0000x reference)
#include <cuda_runtime.h>
#include <cuda_bf16.h>
#include <cstdint>

// MHC layer: B=8192, N=4, C=4096, f32. HBM-bound fusion.
// R14 = R4 chassis (double-buffered cp.async, 1024 thr, 8 rows/CTA,
// grid=1024, float4 STG) + critical-path fix: the 4x4 mix (P*v) and
// agg*w4 are computed BEFORE the reduce barriers (they don't depend on
// inv_rms); after the barrier only o[i] += hq[i]*inv_rms*aw4 + stores.

#define C_DIM 4096
#define NS 4
#define THREADS 1024            // = C_DIM/4 -> one float4 per stream per thread
#define ROWS_PER_CTA 8
#define EPS 1e-6f
#define ROW_F4 (NS * C_DIM / 4)             // 4096 float4 per row buffer
#define SMEM_BYTES (2 * ROW_F4 * 16)        // 128 KB: two row buffers

__device__ __forceinline__ uint32_t smem_u32(const void* p) {
    uint32_t a;
    asm("{ .reg .u64 t; cvta.to.shared.u64 t, %1; cvt.u32.u64 %0, t; }"
        : "=r"(a) : "l"(p));
    return a;
}

__global__ __launch_bounds__(THREADS, 1)
void mhc_kernel(const float* __restrict__ x,
                const float* __restrict__ w,
                const float* __restrict__ H_pre,
                const float* __restrict__ H_post,
                const float* __restrict__ H_res,
                float* __restrict__ out)
{
    extern __shared__ float4 sx[];          // [2][ROW_F4]
    __shared__ float red[THREADS / 32];
    __shared__ float sp[24];                // [0:4)=hpre [4:8)=hpost [8:24)=P

    const int t = threadIdx.x;
    const int b0 = blockIdx.x * ROWS_PER_CTA;
    const uint32_t sbase = smem_u32(sx);

    // ---- prologue: prefetch first row into buffer 0 ----
    {
        const float4* __restrict__ xr =
            reinterpret_cast<const float4*>(x + (size_t)b0 * NS * C_DIM);
#pragma unroll
        for (int n = 0; n < NS; n++) {
            const int idx = n * THREADS + t;
            asm volatile("cp.async.cg.shared.global [%0], [%1], 16;"
                         :: "r"(sbase + idx * 16), "l"(xr + idx));
        }
        asm volatile("cp.async.commit_group;");
    }

    // ---- thread 0: tiny parameter math into smem while copies fly ----
    if (t == 0) {
#pragma unroll
        for (int n = 0; n < NS; n++) {
            sp[n]     = 1.0f / (1.0f + expf(-H_pre[n]));
            sp[4 + n] = 2.0f / (1.0f + expf(-H_post[n]));
        }
        float P[NS][NS];
#pragma unroll
        for (int i = 0; i < NS; i++)
#pragma unroll
            for (int j = 0; j < NS; j++)
                P[i][j] = expf(H_res[i * NS + j]);
#pragma unroll
        for (int it = 0; it < 3; it++) {
#pragma unroll
            for (int i = 0; i < NS; i++) {
                float inv = 1.0f / (P[i][0] + P[i][1] + P[i][2] + P[i][3] + EPS);
#pragma unroll
                for (int j = 0; j < NS; j++) P[i][j] *= inv;
            }
#pragma unroll
            for (int j = 0; j < NS; j++) {
                float inv = 1.0f / (P[0][j] + P[1][j] + P[2][j] + P[3][j] + EPS);
#pragma unroll
                for (int i = 0; i < NS; i++) P[i][j] *= inv;
            }
        }
#pragma unroll
        for (int i = 0; i < NS; i++)
#pragma unroll
            for (int j = 0; j < NS; j++)
                sp[8 + i * NS + j] = P[i][j];
    }
    __syncthreads();

    // ---- params into registers (kept across the row loop) ----
    const float hp0 = sp[0], hp1 = sp[1], hp2 = sp[2], hp3 = sp[3];
    float Pr[NS][NS], hq[NS];
#pragma unroll
    for (int i = 0; i < NS; i++) {
        hq[i] = sp[4 + i];
#pragma unroll
        for (int j = 0; j < NS; j++) Pr[i][j] = sp[8 + i * NS + j];
    }

    const float4* __restrict__ wr = reinterpret_cast<const float4*>(w);
    const float4 w4 = wr[t];                // loop-invariant weight chunk

    int parity = 0;
#pragma unroll 1
    for (int r = 0; r < ROWS_PER_CTA; r++) {
        const int b = b0 + r;
        const bool has_next = (r + 1 < ROWS_PER_CTA);

        // ---- prefetch next row into the other buffer ----
        if (has_next) {
            const float4* __restrict__ xr =
                reinterpret_cast<const float4*>(x + (size_t)(b + 1) * NS * C_DIM);
            const uint32_t sb = sbase + (1 - parity) * (ROW_F4 * 16);
#pragma unroll
            for (int n = 0; n < NS; n++) {
                const int idx = n * THREADS + t;
                asm volatile("cp.async.cg.shared.global [%0], [%1], 16;"
                             :: "r"(sb + idx * 16), "l"(xr + idx));
            }
            asm volatile("cp.async.commit_group;");
            asm volatile("cp.async.wait_group 1;" ::: "memory");
        } else {
            asm volatile("cp.async.wait_group 0;" ::: "memory");
        }
        __syncthreads();

        const float4* __restrict__ sb = sx + parity * ROW_F4;

        // ---- pass A: gated agg + bf16 round-trip -> sum of squares ----
        const float4 v0 = sb[0 * THREADS + t];
        const float4 v1 = sb[1 * THREADS + t];
        const float4 v2 = sb[2 * THREADS + t];
        const float4 v3 = sb[3 * THREADS + t];
        float ax = hp0*v0.x + hp1*v1.x + hp2*v2.x + hp3*v3.x;
        float ay = hp0*v0.y + hp1*v1.y + hp2*v2.y + hp3*v3.y;
        float az = hp0*v0.z + hp1*v1.z + hp2*v2.z + hp3*v3.z;
        float aw = hp0*v0.w + hp1*v1.w + hp2*v2.w + hp3*v3.w;
        ax = __bfloat162float(__float2bfloat16(ax));
        ay = __bfloat162float(__float2bfloat16(ay));
        az = __bfloat162float(__float2bfloat16(az));
        aw = __bfloat162float(__float2bfloat16(aw));
        float ss = ax*ax + ay*ay + az*az + aw*aw;

        // ---- HOISTED: rms-independent work, overlaps the reduce ----
        // mix o[i] = P*v  (v dies into o: register-neutral)
        float4 o[NS];
#pragma unroll
        for (int i = 0; i < NS; i++) {
            o[i].x = Pr[i][0]*v0.x + Pr[i][1]*v1.x + Pr[i][2]*v2.x + Pr[i][3]*v3.x;
            o[i].y = Pr[i][0]*v0.y + Pr[i][1]*v1.y + Pr[i][2]*v2.y + Pr[i][3]*v3.y;
            o[i].z = Pr[i][0]*v0.z + Pr[i][1]*v1.z + Pr[i][2]*v2.z + Pr[i][3]*v3.z;
            o[i].w = Pr[i][0]*v0.w + Pr[i][1]*v1.w + Pr[i][2]*v2.w + Pr[i][3]*v3.w;
        }
        // aw4 = agg .* w  (agg dies into aw4)
        float4 aw4;
        aw4.x = ax * w4.x; aw4.y = ay * w4.y;
        aw4.z = az * w4.z; aw4.w = aw * w4.w;

        // ---- block reduce (32 warps) ----
#pragma unroll
        for (int off = 16; off > 0; off >>= 1)
            ss += __shfl_xor_sync(0xFFFFFFFFu, ss, off);
        if ((t & 31) == 0) red[t >> 5] = ss;
        __syncthreads();
        if (t < 32) {
            float s = red[t];
#pragma unroll
            for (int off = 16; off > 0; off >>= 1)
                s += __shfl_xor_sync(0xFFFFFFFFu, s, off);
            if (t == 0) red[0] = s;
        }
        __syncthreads();
        const float inv_rms = rsqrtf(red[0] * (1.0f / C_DIM) + EPS);

        // ---- minimal post-barrier tail: o[i] += hq[i]*inv_rms*aw4 ----
        float4* __restrict__ outr =
            reinterpret_cast<float4*>(out + (size_t)b * NS * C_DIM);
#pragma unroll
        for (int i = 0; i < NS; i++) {
            const float s = hq[i] * inv_rms;
            float4 oo = o[i];
            oo.x += s * aw4.x;
            oo.y += s * aw4.y;
            oo.z += s * aw4.z;
            oo.w += s * aw4.w;
            outr[i * THREADS + t] = oo;
        }

        // buffer fully read before next iter prefetches into it
        __syncthreads();
        parity ^= 1;
    }
}

extern "C" void kernel_launch(void* const* d_in, const int* in_sizes, int n_in,
                              void* d_out, int out_size)
{
    const float* x      = (const float*)d_in[0];  // [8192, 4, 4096]
    const float* w      = (const float*)d_in[1];  // [4096]
    const float* H_pre  = (const float*)d_in[2];  // [4]
    const float* H_post = (const float*)d_in[3];  // [4]
    const float* H_res  = (const float*)d_in[4];  // [4, 4]
    float* out = (float*)d_out;                   // [8192, 4, 4096]

    cudaFuncSetAttribute(mhc_kernel,
                         cudaFuncAttributeMaxDynamicSharedMemorySize, SMEM_BYTES);

    const int B = in_sizes[0] / (NS * C_DIM);     // 8192
    mhc_kernel<<<B / ROWS_PER_CTA, THREADS, SMEM_BYTES>>>(x, w, H_pre, H_post, H_res, out);
}

// round 15
// speedup vs baseline: 1.0113x; 1.0113x over previous
#include <cuda_runtime.h>
#include <cuda_bf16.h>
#include <cstdint>

// MHC layer: B=8192, N=4, C=4096, f32. HBM-bound fusion.
// R15 = R4 chassis with ONE barrier per row (was 3):
//  - each thread loads (cp.async) and reads ONLY its own smem slots
//    (idx = n*THREADS + t), so wait_group alone gives visibility: the
//    post-wait barrier and trailing buffer barrier are unnecessary.
//  - reduce: warp partials -> parity-double-buffered red4 -> ONE
//    __syncthreads -> every thread sums the 32 partials (broadcast LDS).
//  - R14 hoist kept: P*v mix and agg*w computed before the barrier.

#define C_DIM 4096
#define NS 4
#define THREADS 1024            // = C_DIM/4 -> one float4 per stream per thread
#define ROWS_PER_CTA 8
#define EPS 1e-6f
#define ROW_F4 (NS * C_DIM / 4)             // 4096 float4 per row buffer
#define SMEM_BYTES (2 * ROW_F4 * 16)        // 128 KB: two row buffers

__device__ __forceinline__ uint32_t smem_u32(const void* p) {
    uint32_t a;
    asm("{ .reg .u64 t; cvta.to.shared.u64 t, %1; cvt.u32.u64 %0, t; }"
        : "=r"(a) : "l"(p));
    return a;
}

__global__ __launch_bounds__(THREADS, 1)
void mhc_kernel(const float* __restrict__ x,
                const float* __restrict__ w,
                const float* __restrict__ H_pre,
                const float* __restrict__ H_post,
                const float* __restrict__ H_res,
                float* __restrict__ out)
{
    extern __shared__ float4 sx[];          // [2][ROW_F4]
    __shared__ float4 red4[2][THREADS / 32 / 4];   // [parity][8] = 32 floats
    __shared__ float sp[24];                // [0:4)=hpre [4:8)=hpost [8:24)=P

    const int t = threadIdx.x;
    const int b0 = blockIdx.x * ROWS_PER_CTA;
    const uint32_t sbase = smem_u32(sx);

    // ---- prologue: prefetch first row into buffer 0 ----
    {
        const float4* __restrict__ xr =
            reinterpret_cast<const float4*>(x + (size_t)b0 * NS * C_DIM);
#pragma unroll
        for (int n = 0; n < NS; n++) {
            const int idx = n * THREADS + t;
            asm volatile("cp.async.cg.shared.global [%0], [%1], 16;"
                         :: "r"(sbase + idx * 16), "l"(xr + idx));
        }
        asm volatile("cp.async.commit_group;");
    }

    // ---- thread 0: tiny parameter math into smem while copies fly ----
    if (t == 0) {
#pragma unroll
        for (int n = 0; n < NS; n++) {
            sp[n]     = 1.0f / (1.0f + expf(-H_pre[n]));
            sp[4 + n] = 2.0f / (1.0f + expf(-H_post[n]));
        }
        float P[NS][NS];
#pragma unroll
        for (int i = 0; i < NS; i++)
#pragma unroll
            for (int j = 0; j < NS; j++)
                P[i][j] = expf(H_res[i * NS + j]);
#pragma unroll
        for (int it = 0; it < 3; it++) {
#pragma unroll
            for (int i = 0; i < NS; i++) {
                float inv = 1.0f / (P[i][0] + P[i][1] + P[i][2] + P[i][3] + EPS);
#pragma unroll
                for (int j = 0; j < NS; j++) P[i][j] *= inv;
            }
#pragma unroll
            for (int j = 0; j < NS; j++) {
                float inv = 1.0f / (P[0][j] + P[1][j] + P[2][j] + P[3][j] + EPS);
#pragma unroll
                for (int i = 0; i < NS; i++) P[i][j] *= inv;
            }
        }
#pragma unroll
        for (int i = 0; i < NS; i++)
#pragma unroll
            for (int j = 0; j < NS; j++)
                sp[8 + i * NS + j] = P[i][j];
    }
    __syncthreads();   // params visible (once, prologue only)

    // ---- params into registers (kept across the row loop) ----
    const float hp0 = sp[0], hp1 = sp[1], hp2 = sp[2], hp3 = sp[3];
    float Pr[NS][NS], hq[NS];
#pragma unroll
    for (int i = 0; i < NS; i++) {
        hq[i] = sp[4 + i];
#pragma unroll
        for (int j = 0; j < NS; j++) Pr[i][j] = sp[8 + i * NS + j];
    }

    const float4* __restrict__ wr = reinterpret_cast<const float4*>(w);
    const float4 w4 = wr[t];                // loop-invariant weight chunk

    int parity = 0;
#pragma unroll 1
    for (int r = 0; r < ROWS_PER_CTA; r++) {
        const int b = b0 + r;
        const bool has_next = (r + 1 < ROWS_PER_CTA);
        const int par = r & 1;

        // ---- prefetch next row into the other buffer ----
        // Own-slot discipline: this thread only overwrites smem it alone
        // reads, and it has already read those slots (sequential exec).
        if (has_next) {
            const float4* __restrict__ xr =
                reinterpret_cast<const float4*>(x + (size_t)(b + 1) * NS * C_DIM);
            const uint32_t sb = sbase + (1 - parity) * (ROW_F4 * 16);
#pragma unroll
            for (int n = 0; n < NS; n++) {
                const int idx = n * THREADS + t;
                asm volatile("cp.async.cg.shared.global [%0], [%1], 16;"
                             :: "r"(sb + idx * 16), "l"(xr + idx));
            }
            asm volatile("cp.async.commit_group;");
            asm volatile("cp.async.wait_group 1;" ::: "memory");
        } else {
            asm volatile("cp.async.wait_group 0;" ::: "memory");
        }
        // NO barrier: each thread reads only the slots it cp.async'd.

        const float4* __restrict__ sb = sx + parity * ROW_F4;

        // ---- pass A: gated agg + bf16 round-trip -> sum of squares ----
        const float4 v0 = sb[0 * THREADS + t];
        const float4 v1 = sb[1 * THREADS + t];
        const float4 v2 = sb[2 * THREADS + t];
        const float4 v3 = sb[3 * THREADS + t];
        float ax = hp0*v0.x + hp1*v1.x + hp2*v2.x + hp3*v3.x;
        float ay = hp0*v0.y + hp1*v1.y + hp2*v2.y + hp3*v3.y;
        float az = hp0*v0.z + hp1*v1.z + hp2*v2.z + hp3*v3.z;
        float aw = hp0*v0.w + hp1*v1.w + hp2*v2.w + hp3*v3.w;
        ax = __bfloat162float(__float2bfloat16(ax));
        ay = __bfloat162float(__float2bfloat16(ay));
        az = __bfloat162float(__float2bfloat16(az));
        aw = __bfloat162float(__float2bfloat16(aw));
        float ss = ax*ax + ay*ay + az*az + aw*aw;

        // ---- hoisted rms-independent work (overlaps the barrier) ----
        float4 o[NS];
#pragma unroll
        for (int i = 0; i < NS; i++) {
            o[i].x = Pr[i][0]*v0.x + Pr[i][1]*v1.x + Pr[i][2]*v2.x + Pr[i][3]*v3.x;
            o[i].y = Pr[i][0]*v0.y + Pr[i][1]*v1.y + Pr[i][2]*v2.y + Pr[i][3]*v3.y;
            o[i].z = Pr[i][0]*v0.z + Pr[i][1]*v1.z + Pr[i][2]*v2.z + Pr[i][3]*v3.z;
            o[i].w = Pr[i][0]*v0.w + Pr[i][1]*v1.w + Pr[i][2]*v2.w + Pr[i][3]*v3.w;
        }
        float4 aw4;
        aw4.x = ax * w4.x; aw4.y = ay * w4.y;
        aw4.z = az * w4.z; aw4.w = aw * w4.w;

        // ---- reduce: warp partials -> ONE barrier -> all-thread sum ----
#pragma unroll
        for (int off = 16; off > 0; off >>= 1)
            ss += __shfl_xor_sync(0xFFFFFFFFu, ss, off);
        if ((t & 31) == 0)
            reinterpret_cast<float*>(red4[par])[t >> 5] = ss;

        __syncthreads();   // the ONE barrier per row

        float4 acc = red4[par][0];
#pragma unroll
        for (int q = 1; q < 8; q++) {
            const float4 p = red4[par][q];
            acc.x += p.x; acc.y += p.y; acc.z += p.z; acc.w += p.w;
        }
        const float inv_rms =
            rsqrtf(((acc.x + acc.y) + (acc.z + acc.w)) * (1.0f / C_DIM) + EPS);

        // ---- minimal tail: o[i] += hq[i]*inv_rms*aw4, float4 stores ----
        float4* __restrict__ outr =
            reinterpret_cast<float4*>(out + (size_t)b * NS * C_DIM);
#pragma unroll
        for (int i = 0; i < NS; i++) {
            const float s = hq[i] * inv_rms;
            float4 oo = o[i];
            oo.x += s * aw4.x;
            oo.y += s * aw4.y;
            oo.z += s * aw4.z;
            oo.w += s * aw4.w;
            outr[i * THREADS + t] = oo;
        }

        parity ^= 1;
        // NO trailing barrier (own-slot discipline; red4 parity-buffered,
        // and the next barrier orders partial reads before overwrite).
    }
}

extern "C" void kernel_launch(void* const* d_in, const int* in_sizes, int n_in,
                              void* d_out, int out_size)
{
    const float* x      = (const float*)d_in[0];  // [8192, 4, 4096]
    const float* w      = (const float*)d_in[1];  // [4096]
    const float* H_pre  = (const float*)d_in[2];  // [4]
    const float* H_post = (const float*)d_in[3];  // [4]
    const float* H_res  = (const float*)d_in[4];  // [4, 4]
    float* out = (float*)d_out;                   // [8192, 4, 4096]

    cudaFuncSetAttribute(mhc_kernel,
                         cudaFuncAttributeMaxDynamicSharedMemorySize, SMEM_BYTES);

    const int B = in_sizes[0] / (NS * C_DIM);     // 8192
    mhc_kernel<<<B / ROWS_PER_CTA, THREADS, SMEM_BYTES>>>(x, w, H_pre, H_post, H_res, out);
}